// round 4
// baseline (speedup 1.0000x reference)
#include <cuda_runtime.h>
#include <cuda_bf16.h>

// Fixed problem shapes
#define NBOX 256
#define CPL  256
#define UH   200
#define UW   304
#define H1   100
#define W1   152
#define H2   50
#define W2   76

#define TPB 512   // 8 channel-lanes x 64 slots (49 active) -> warp == one plane

__global__ void __launch_bounds__(TPB, 2)
fused_roialign_kernel(const float* __restrict__ feat0,
                      const float* __restrict__ feat1,
                      const float* __restrict__ feat2,
                      const float* __restrict__ boxes,
                      float* __restrict__ out)
{
    const int n   = blockIdx.x;
    const int lvl = blockIdx.y;
    const int tid = threadIdx.x;

    // Level-0 scalar tap tables (fallback for big boxes): [axis][pos][tap]
    __shared__ float s_w0[2][7][4];
    __shared__ int   s_i0[2][7][4];
    // Dense windows (coarse levels always; level 0 when fast): x = 8 cols, y <= 6 rows
    __shared__ float s_xw[7][8];
    __shared__ int   s_xb[7];
    __shared__ int   s_x2[7];    // second float4 needed?
    __shared__ float s_yw[7][6];
    __shared__ int   s_yb[7];
    __shared__ int   s_yn[7];    // true row count

    // fast-path eligibility for level 0 (uniform per block; cheap per-thread)
    const float rbx = fmaxf((boxes[n * 4 + 2] - boxes[n * 4 + 0]) * 0.25f, 1.0f);
    const float rby = fmaxf((boxes[n * 4 + 3] - boxes[n * 4 + 1]) * 0.25f, 1.0f);
    const bool  fast0 = (rbx <= 42.0f) && (rby <= 56.0f);

    if (tid < 14) {
        const int axis = tid / 7;          // 0 = x, 1 = y
        const int p    = tid % 7;
        const float b1 = boxes[n * 4 + axis] * 0.25f;
        const float rb = axis ? rby : rbx;
        const float bt = rb * (1.0f / 7.0f);
        const int updim = axis ? UH : UW;

        if (lvl == 0 && !fast0) {
            // scalar 4-tap tables
            #pragma unroll
            for (int s = 0; s < 2; s++) {
                float T  = b1 + ((float)p + 0.25f + 0.5f * (float)s) * bt;
                float Tc = fminf(fmaxf(T, 0.0f), (float)(updim - 1));
                int   i0 = (int)Tc;
                int   i1 = min(i0 + 1, updim - 1);
                float f  = Tc - (float)i0;
                s_i0[axis][p][2 * s + 0] = i0;
                s_i0[axis][p][2 * s + 1] = i1;
                s_w0[axis][p][2 * s + 0] = 0.5f * (1.0f - f);
                s_w0[axis][p][2 * s + 1] = 0.5f * f;
            }
        } else {
            // dense window build: collect (index, weight) taps, then bin
            int   ci[8];
            float cw[8];
            int   e  = 0;
            int   mn = 1 << 30;
            if (lvl == 0) {
                // direct bilinear taps (no upsample indirection)
                #pragma unroll
                for (int s = 0; s < 2; s++) {
                    float T  = b1 + ((float)p + 0.25f + 0.5f * (float)s) * bt;
                    float Tc = fminf(fmaxf(T, 0.0f), (float)(updim - 1));
                    int   i0 = (int)Tc;
                    int   i1 = min(i0 + 1, updim - 1);
                    float f  = Tc - (float)i0;
                    ci[e] = i0; cw[e] = 0.5f * (1.0f - f); e++;
                    ci[e] = i1; cw[e] = 0.5f * f;          e++;
                    mn = min(mn, i0);
                }
            } else {
                const float inv  = (lvl == 1) ? 0.5f : 0.25f;
                const int   cdim = axis ? ((lvl == 1) ? H1 : H2)
                                        : ((lvl == 1) ? W1 : W2);
                #pragma unroll
                for (int s = 0; s < 2; s++) {
                    float T  = b1 + ((float)p + 0.25f + 0.5f * (float)s) * bt;
                    float Tc = fminf(fmaxf(T, 0.0f), (float)(updim - 1));
                    int   u0 = (int)Tc;
                    int   u1 = min(u0 + 1, updim - 1);
                    float fu = Tc - (float)u0;
                    #pragma unroll
                    for (int b = 0; b < 2; b++) {
                        int   u  = b ? u1 : u0;
                        float wu = b ? (0.5f * fu) : (0.5f * (1.0f - fu));
                        float g  = ((float)u + 0.5f) * inv - 0.5f;
                        g = fminf(fmaxf(g, 0.0f), (float)(cdim - 1));
                        int   c0 = (int)g;
                        int   c1 = min(c0 + 1, cdim - 1);
                        float fc = g - (float)c0;
                        ci[e] = c0; cw[e] = wu * (1.0f - fc); e++;
                        ci[e] = c1; cw[e] = wu * fc;          e++;
                        mn = min(mn, c0);
                    }
                }
            }
            const int ntap = e;
            const int cdim = (lvl == 0) ? updim
                           : (axis ? ((lvl == 1) ? H1 : H2)
                                   : ((lvl == 1) ? W1 : W2));
            if (axis == 0) {
                int xb = min(mn & ~3, cdim - 8);
                float w[8] = {0, 0, 0, 0, 0, 0, 0, 0};
                for (int k = 0; k < ntap; k++) {
                    int off = min(max(ci[k] - xb, 0), 7);
                    w[off] += cw[k];
                }
                s_xb[p] = xb;
                int need2 = 0;
                #pragma unroll
                for (int k = 0; k < 8; k++) {
                    s_xw[p][k] = w[k];
                    if (k >= 4 && w[k] != 0.0f) need2 = 1;
                }
                s_x2[p] = need2;
            } else {
                const int R = 6;
                int yb = min(mn, cdim - R);
                float w[6] = {0, 0, 0, 0, 0, 0};
                for (int k = 0; k < ntap; k++) {
                    int off = min(max(ci[k] - yb, 0), R - 1);
                    w[off] += cw[k];
                }
                s_yb[p] = yb;
                int rn = 1;
                #pragma unroll
                for (int k = 0; k < 6; k++) {
                    s_yw[p][k] = w[k];
                    if (w[k] != 0.0f) rn = k + 1;
                }
                s_yn[p] = rn;
            }
        }
    }
    __syncthreads();

    const int slot = tid & 63;
    if (slot >= 49) return;
    const int cl   = tid >> 6;                  // 0..7 channel lane
    const int cell = slot;
    const int oh   = cell / 7;
    const int ow   = cell % 7;
    float* op = out + ((size_t)(n * 768 + lvl * CPL) * 49) + cell;

    if (lvl == 0 && !fast0) {
        int   xi0 = s_i0[0][ow][0], xi1 = s_i0[0][ow][1], xi2 = s_i0[0][ow][2], xi3 = s_i0[0][ow][3];
        float xw0 = s_w0[0][ow][0], xw1 = s_w0[0][ow][1], xw2 = s_w0[0][ow][2], xw3 = s_w0[0][ow][3];
        int   ro0 = s_i0[1][oh][0] * UW, ro1 = s_i0[1][oh][1] * UW,
              ro2 = s_i0[1][oh][2] * UW, ro3 = s_i0[1][oh][3] * UW;
        float yw0 = s_w0[1][oh][0], yw1 = s_w0[1][oh][1], yw2 = s_w0[1][oh][2], yw3 = s_w0[1][oh][3];

        for (int c = cl; c < CPL; c += 8) {
            const float* pl = feat0 + c * (UH * UW);
            const float* r0 = pl + ro0;
            const float* r1 = pl + ro1;
            const float* r2 = pl + ro2;
            const float* r3 = pl + ro3;
            float s0 = xw0 * __ldg(r0 + xi0) + xw1 * __ldg(r0 + xi1)
                     + xw2 * __ldg(r0 + xi2) + xw3 * __ldg(r0 + xi3);
            float s1 = xw0 * __ldg(r1 + xi0) + xw1 * __ldg(r1 + xi1)
                     + xw2 * __ldg(r1 + xi2) + xw3 * __ldg(r1 + xi3);
            float s2 = xw0 * __ldg(r2 + xi0) + xw1 * __ldg(r2 + xi1)
                     + xw2 * __ldg(r2 + xi2) + xw3 * __ldg(r2 + xi3);
            float s3 = xw0 * __ldg(r3 + xi0) + xw1 * __ldg(r3 + xi1)
                     + xw2 * __ldg(r3 + xi2) + xw3 * __ldg(r3 + xi3);
            op[c * 49] = yw0 * s0 + yw1 * s1 + yw2 * s2 + yw3 * s3;
        }
    } else {
        const float* base;
        int W_, cstr;
        if (lvl == 0)      { base = feat0; W_ = UW; cstr = UH * UW; }
        else if (lvl == 1) { base = feat1; W_ = W1; cstr = H1 * W1; }
        else               { base = feat2; W_ = W2; cstr = H2 * W2; }

        const int xb = s_xb[ow];
        const int yb = s_yb[oh];
        const int need2 = s_x2[ow];
        const int rN = s_yn[oh];
        float xw[8], yw[6];
        #pragma unroll
        for (int k = 0; k < 8; k++) xw[k] = s_xw[ow][k];
        #pragma unroll
        for (int k = 0; k < 6; k++) yw[k] = s_yw[oh][k];

        for (int c = cl; c < CPL; c += 8) {
            const float* pl = base + c * cstr + yb * W_ + xb;
            float acc = 0.0f;
            #pragma unroll 6
            for (int r = 0; r < rN; r++) {
                const float4* row = (const float4*)(pl + r * W_);
                float4 a = __ldg(row);
                float rs = xw[0] * a.x + xw[1] * a.y + xw[2] * a.z + xw[3] * a.w;
                if (need2) {
                    float4 b = __ldg(row + 1);
                    rs += xw[4] * b.x + xw[5] * b.y + xw[6] * b.z + xw[7] * b.w;
                }
                acc = fmaf(yw[r], rs, acc);
            }
            op[c * 49] = acc;
        }
    }
}

extern "C" void kernel_launch(void* const* d_in, const int* in_sizes, int n_in,
                              void* d_out, int out_size) {
    const float* feat0 = (const float*)d_in[0];
    const float* feat1 = (const float*)d_in[1];
    const float* feat2 = (const float*)d_in[2];
    const float* boxes = (const float*)d_in[3];
    float* out = (float*)d_out;

    dim3 grid(NBOX, 3);
    fused_roialign_kernel<<<grid, TPB>>>(feat0, feat1, feat2, boxes, out);
}

// round 5
// speedup vs baseline: 1.2001x; 1.2001x over previous
#include <cuda_runtime.h>
#include <cuda_bf16.h>

// Fixed problem shapes
#define NBOX 256
#define CPL  256
#define UH   200
#define UW   304
#define H1   100
#define W1   152
#define H2   50
#define W2   76

#define TPB 512   // 8 channel-lanes x 64 slots (49 active): no warp straddles planes

__global__ void __launch_bounds__(TPB, 2)
fused_roialign_kernel(const float* __restrict__ feat0,
                      const float* __restrict__ feat1,
                      const float* __restrict__ feat2,
                      const float* __restrict__ boxes,
                      float* __restrict__ out)
{
    const int n    = blockIdx.x;
    const int lvl  = blockIdx.y >> 1;     // 0,1,2
    const int half = blockIdx.y & 1;      // channel half
    const int tid  = threadIdx.x;

    // Level-0 tap tables: [axis][pos][tap]
    __shared__ float s_w0[2][7][4];
    __shared__ int   s_i0[2][7][4];
    // Coarse-level windows: x = 8 cols (two float4), y = up to 5 rows
    __shared__ float s_xw[7][8];
    __shared__ int   s_xb[7];
    __shared__ float s_yw[7][5];
    __shared__ int   s_yb[7];

    if (tid < 14) {
        const int axis = tid / 7;          // 0 = x, 1 = y
        const int p    = tid % 7;
        float b1 = boxes[n * 4 + axis]     * 0.25f;
        float b2 = boxes[n * 4 + 2 + axis] * 0.25f;
        float rb = fmaxf(b2 - b1, 1.0f);
        float bt = rb * (1.0f / 7.0f);
        const int updim = axis ? UH : UW;

        if (lvl == 0) {
            #pragma unroll
            for (int s = 0; s < 2; s++) {
                float T  = b1 + ((float)p + 0.25f + 0.5f * (float)s) * bt;
                float Tc = fminf(fmaxf(T, 0.0f), (float)(updim - 1));
                int   i0 = (int)Tc;
                int   i1 = min(i0 + 1, updim - 1);
                float f  = Tc - (float)i0;
                s_i0[axis][p][2 * s + 0] = i0;
                s_i0[axis][p][2 * s + 1] = i1;
                s_w0[axis][p][2 * s + 0] = 0.5f * (1.0f - f);
                s_w0[axis][p][2 * s + 1] = 0.5f * f;
            }
        } else {
            const float inv  = (lvl == 1) ? 0.5f : 0.25f;
            const int   cdim = axis ? ((lvl == 1) ? H1 : H2)
                                    : ((lvl == 1) ? W1 : W2);
            const int   R    = (lvl == 1) ? 5 : 4;   // worst-case distinct rows
            int   ci[8];
            float cw[8];
            int   mn = 1 << 30;
            int   e  = 0;
            #pragma unroll
            for (int s = 0; s < 2; s++) {
                float T  = b1 + ((float)p + 0.25f + 0.5f * (float)s) * bt;
                float Tc = fminf(fmaxf(T, 0.0f), (float)(updim - 1));
                int   u0 = (int)Tc;
                int   u1 = min(u0 + 1, updim - 1);
                float fu = Tc - (float)u0;
                #pragma unroll
                for (int b = 0; b < 2; b++) {
                    int   u  = b ? u1 : u0;
                    float wu = b ? (0.5f * fu) : (0.5f * (1.0f - fu));
                    float g  = ((float)u + 0.5f) * inv - 0.5f;
                    g = fminf(fmaxf(g, 0.0f), (float)(cdim - 1));
                    int   c0 = (int)g;
                    int   c1 = min(c0 + 1, cdim - 1);
                    float fc = g - (float)c0;
                    ci[e] = c0; cw[e] = wu * (1.0f - fc); e++;
                    ci[e] = c1; cw[e] = wu * fc;          e++;
                    mn = min(mn, c0);
                }
            }
            if (axis == 0) {
                int xb = min(mn & ~3, cdim - 8);   // float4-aligned window of 8
                float w[8] = {0, 0, 0, 0, 0, 0, 0, 0};
                #pragma unroll
                for (int k = 0; k < 8; k++) {
                    int off = min(max(ci[k] - xb, 0), 7);
                    w[off] += cw[k];
                }
                s_xb[p] = xb;
                #pragma unroll
                for (int k = 0; k < 8; k++) s_xw[p][k] = w[k];
            } else {
                int yb = min(mn, cdim - R);        // R rows in-bounds
                float w[5] = {0, 0, 0, 0, 0};
                #pragma unroll
                for (int k = 0; k < 8; k++) {
                    int off = min(max(ci[k] - yb, 0), R - 1);
                    w[off] += cw[k];
                }
                s_yb[p] = yb;
                #pragma unroll
                for (int k = 0; k < 5; k++) s_yw[p][k] = w[k];
            }
        }
    }
    __syncthreads();

    const int slot = tid & 63;
    if (slot >= 49) return;
    const int cl   = tid >> 6;                // 0..7 channel lane
    const int cbase = half * 128 + cl;        // this thread's first channel
    const int oh   = slot / 7;
    const int ow   = slot % 7;
    float* op = out + ((size_t)(n * 768 + lvl * CPL) * 49) + slot;

    if (lvl == 0) {
        int   xi0 = s_i0[0][ow][0], xi1 = s_i0[0][ow][1], xi2 = s_i0[0][ow][2], xi3 = s_i0[0][ow][3];
        float xw0 = s_w0[0][ow][0], xw1 = s_w0[0][ow][1], xw2 = s_w0[0][ow][2], xw3 = s_w0[0][ow][3];
        int   ro0 = s_i0[1][oh][0] * UW, ro1 = s_i0[1][oh][1] * UW,
              ro2 = s_i0[1][oh][2] * UW, ro3 = s_i0[1][oh][3] * UW;
        float yw0 = s_w0[1][oh][0], yw1 = s_w0[1][oh][1], yw2 = s_w0[1][oh][2], yw3 = s_w0[1][oh][3];

        #pragma unroll 2
        for (int k = 0; k < 16; k++) {
            const int c = cbase + 8 * k;
            const float* pl = feat0 + c * (UH * UW);
            const float* r0 = pl + ro0;
            const float* r1 = pl + ro1;
            const float* r2 = pl + ro2;
            const float* r3 = pl + ro3;
            float s0 = xw0 * __ldg(r0 + xi0) + xw1 * __ldg(r0 + xi1)
                     + xw2 * __ldg(r0 + xi2) + xw3 * __ldg(r0 + xi3);
            float s1 = xw0 * __ldg(r1 + xi0) + xw1 * __ldg(r1 + xi1)
                     + xw2 * __ldg(r1 + xi2) + xw3 * __ldg(r1 + xi3);
            float s2 = xw0 * __ldg(r2 + xi0) + xw1 * __ldg(r2 + xi1)
                     + xw2 * __ldg(r2 + xi2) + xw3 * __ldg(r2 + xi3);
            float s3 = xw0 * __ldg(r3 + xi0) + xw1 * __ldg(r3 + xi1)
                     + xw2 * __ldg(r3 + xi2) + xw3 * __ldg(r3 + xi3);
            op[c * 49] = yw0 * s0 + yw1 * s1 + yw2 * s2 + yw3 * s3;
        }
    } else if (lvl == 1) {
        const int xb = s_xb[ow];
        const int yb = s_yb[oh];
        float xw[8], yw[5];
        #pragma unroll
        for (int k = 0; k < 8; k++) xw[k] = s_xw[ow][k];
        #pragma unroll
        for (int k = 0; k < 5; k++) yw[k] = s_yw[oh][k];

        #pragma unroll 2
        for (int k = 0; k < 16; k++) {
            const int c = cbase + 8 * k;
            const float* pl = feat1 + c * (H1 * W1) + yb * W1 + xb;
            float acc = 0.0f;
            #pragma unroll
            for (int r = 0; r < 5; r++) {
                const float4* row = (const float4*)(pl + r * W1);
                float4 a = __ldg(row);
                float4 b = __ldg(row + 1);
                float rs = xw[0] * a.x + xw[1] * a.y + xw[2] * a.z + xw[3] * a.w
                         + xw[4] * b.x + xw[5] * b.y + xw[6] * b.z + xw[7] * b.w;
                acc = fmaf(yw[r], rs, acc);
            }
            op[c * 49] = acc;
        }
    } else {
        const int xb = s_xb[ow];
        const int yb = s_yb[oh];
        float xw[8], yw[4];
        #pragma unroll
        for (int k = 0; k < 8; k++) xw[k] = s_xw[ow][k];
        #pragma unroll
        for (int k = 0; k < 4; k++) yw[k] = s_yw[oh][k];

        #pragma unroll 2
        for (int k = 0; k < 16; k++) {
            const int c = cbase + 8 * k;
            const float* pl = feat2 + c * (H2 * W2) + yb * W2 + xb;
            float acc = 0.0f;
            #pragma unroll
            for (int r = 0; r < 4; r++) {
                const float4* row = (const float4*)(pl + r * W2);
                float4 a = __ldg(row);
                float4 b = __ldg(row + 1);
                float rs = xw[0] * a.x + xw[1] * a.y + xw[2] * a.z + xw[3] * a.w
                         + xw[4] * b.x + xw[5] * b.y + xw[6] * b.z + xw[7] * b.w;
                acc = fmaf(yw[r], rs, acc);
            }
            op[c * 49] = acc;
        }
    }
}

extern "C" void kernel_launch(void* const* d_in, const int* in_sizes, int n_in,
                              void* d_out, int out_size) {
    const float* feat0 = (const float*)d_in[0];
    const float* feat1 = (const float*)d_in[1];
    const float* feat2 = (const float*)d_in[2];
    const float* boxes = (const float*)d_in[3];
    float* out = (float*)d_out;

    dim3 grid(NBOX, 6);
    fused_roialign_kernel<<<grid, TPB>>>(feat0, feat1, feat2, boxes, out);
}